// round 1
// baseline (speedup 1.0000x reference)
#include <cuda_runtime.h>
#include <cuda_bf16.h>

// Neural-ODE explicit Euler, 20 steps, fused persistent kernel.
// B=8192, LATENT=256, U=16, HIDDEN=512.
// Each CTA owns TM=32 batch rows; z lives in SMEM across all steps.
// Weights (W1: 272x512, W2: 512x256, fp32, ~1.08MB) are read from L2 every
// k-iteration; b1/b2 via L1.
//
// Layouts:
//   Zs: k-major [256][33] (pad 33 -> conflict-free update writes & transposed IO)
//   Hs: row-major [32][512] (reads are warp-broadcast; writes lane-consecutive)
//   Us: k-major [16][32]

#define NSTEPS   20
#define TM       32
#define LATENT   256
#define UDIM     16
#define HIDDEN   512
#define ZS_STRIDE 33
#define THREADS  256

__global__ __launch_bounds__(THREADS, 2)
void node_euler_kernel(const float* __restrict__ zt,
                       const float* __restrict__ dt,
                       const float* __restrict__ ut,
                       const float* __restrict__ W1,
                       const float* __restrict__ b1,
                       const float* __restrict__ W2,
                       const float* __restrict__ b2,
                       float* __restrict__ out)
{
    extern __shared__ float smem[];
    float* Zs    = smem;                               // [LATENT][ZS_STRIDE]
    float* Hs    = Zs + LATENT * ZS_STRIDE;            // [TM][HIDDEN]
    float* Us    = Hs + TM * HIDDEN;                   // [UDIM][TM]
    float* hstep = Us + UDIM * TM;                     // [TM]

    const int tid  = threadIdx.x;
    const int tx   = tid & 31;        // 0..31 (lane)
    const int ty   = tid >> 5;        // 0..7  (warp)
    const int row0 = blockIdx.x * TM;

    // ---- Load z tile (transposed into k-major Zs) ----
    for (int idx = tid; idx < TM * LATENT; idx += THREADS) {
        int r = idx >> 8;           // idx / 256
        int k = idx & 255;          // idx % 256
        Zs[k * ZS_STRIDE + r] = zt[(row0 + r) * LATENT + k];
    }
    // ---- Load u tile (k-major) ----
    for (int idx = tid; idx < TM * UDIM; idx += THREADS) {
        int r = idx >> 4;
        int k = idx & 15;
        Us[k * TM + r] = ut[(row0 + r) * UDIM + k];
    }
    // ---- Per-row step size h = dt/NSTEPS ----
    if (tid < TM) hstep[tid] = dt[row0 + tid] * (1.0f / NSTEPS);
    __syncthreads();

    const int rbase = ty * 4;   // this thread's 4 rows

    for (int s = 0; s < NSTEPS; s++) {
        // ================= GEMM1: H = tanh(X @ W1 + b1) =================
        // Thread tile: 4 rows x 16 cols (cols = tx + 32*j), 64 accumulators.
        float acc[16][4];
        #pragma unroll
        for (int j = 0; j < 16; j++) {
            float bv = b1[tx + 32 * j];
            #pragma unroll
            for (int r = 0; r < 4; r++) acc[j][r] = bv;
        }

        // K over latent part (z)
        #pragma unroll 2
        for (int k = 0; k < LATENT; k++) {
            float xr[4];
            #pragma unroll
            for (int r = 0; r < 4; r++)
                xr[r] = Zs[k * ZS_STRIDE + rbase + r];  // warp-broadcast
            const float* w = W1 + k * HIDDEN + tx;
            #pragma unroll
            for (int j = 0; j < 16; j++) {
                float wv = __ldg(w + 32 * j);            // 128B coalesced
                #pragma unroll
                for (int r = 0; r < 4; r++) acc[j][r] += wv * xr[r];
            }
        }
        // K over control part (u)
        #pragma unroll
        for (int k = 0; k < UDIM; k++) {
            float xr[4];
            #pragma unroll
            for (int r = 0; r < 4; r++)
                xr[r] = Us[k * TM + rbase + r];
            const float* w = W1 + (LATENT + k) * HIDDEN + tx;
            #pragma unroll
            for (int j = 0; j < 16; j++) {
                float wv = __ldg(w + 32 * j);
                #pragma unroll
                for (int r = 0; r < 4; r++) acc[j][r] += wv * xr[r];
            }
        }

        // tanh + store H (row-major; lanes write consecutive floats)
        #pragma unroll
        for (int j = 0; j < 16; j++) {
            #pragma unroll
            for (int r = 0; r < 4; r++) {
                Hs[(rbase + r) * HIDDEN + tx + 32 * j] = tanhf(acc[j][r]);
            }
        }
        __syncthreads();

        // ================= GEMM2: F = H @ W2 + b2;  z += h*F =================
        // Thread tile: 4 rows x 8 cols (cols = tx + 32*j), 32 accumulators.
        float acc2[8][4];
        #pragma unroll
        for (int j = 0; j < 8; j++) {
            float bv = b2[tx + 32 * j];
            #pragma unroll
            for (int r = 0; r < 4; r++) acc2[j][r] = bv;
        }

        #pragma unroll 2
        for (int k = 0; k < HIDDEN; k++) {
            float hr[4];
            #pragma unroll
            for (int r = 0; r < 4; r++)
                hr[r] = Hs[(rbase + r) * HIDDEN + k];    // warp-broadcast
            const float* w = W2 + k * LATENT + tx;
            #pragma unroll
            for (int j = 0; j < 8; j++) {
                float wv = __ldg(w + 32 * j);            // 128B coalesced
                #pragma unroll
                for (int r = 0; r < 4; r++) acc2[j][r] += wv * hr[r];
            }
        }

        // z update: Zs[col][row] += h[row] * F   (bank stride 33 -> conflict-free)
        #pragma unroll
        for (int j = 0; j < 8; j++) {
            int col = tx + 32 * j;
            #pragma unroll
            for (int r = 0; r < 4; r++) {
                int rr = rbase + r;
                Zs[col * ZS_STRIDE + rr] += hstep[rr] * acc2[j][r];
            }
        }
        __syncthreads();
    }

    // ---- Store z tile back (coalesced writes) ----
    for (int idx = tid; idx < TM * LATENT; idx += THREADS) {
        int r = idx >> 8;
        int k = idx & 255;
        out[(row0 + r) * LATENT + k] = Zs[k * ZS_STRIDE + r];
    }
}

extern "C" void kernel_launch(void* const* d_in, const int* in_sizes, int n_in,
                              void* d_out, int out_size)
{
    const float* zt = (const float*)d_in[0];
    const float* dt = (const float*)d_in[1];
    const float* ut = (const float*)d_in[2];
    const float* W1 = (const float*)d_in[3];
    const float* b1 = (const float*)d_in[4];
    const float* W2 = (const float*)d_in[5];
    const float* b2 = (const float*)d_in[6];
    float* out = (float*)d_out;

    const int B = 8192;
    const int grid = B / TM;   // 256 CTAs

    size_t smem_bytes = (size_t)(LATENT * ZS_STRIDE + TM * HIDDEN + UDIM * TM + TM) * sizeof(float);

    cudaFuncSetAttribute(node_euler_kernel,
                         cudaFuncAttributeMaxDynamicSharedMemorySize,
                         (int)smem_bytes);

    node_euler_kernel<<<grid, THREADS, smem_bytes>>>(zt, dt, ut, W1, b1, W2, b2, out);
}

// round 2
// speedup vs baseline: 1.0028x; 1.0028x over previous
#include <cuda_runtime.h>
#include <cuda_bf16.h>

// Neural-ODE explicit Euler, 20 steps, fused persistent kernel.
// B=8192, LATENT=256, U=16, HIDDEN=512.
// Each CTA owns TM=32 batch rows; z lives in SMEM across all steps.
// Weights (W1: 272x512, W2: 512x256, fp32, ~1.08MB) are read from L2 every
// k-iteration; b1/b2 via L1.
//
// Layouts:
//   Zs: k-major [256][33] (pad 33 -> conflict-free update writes & transposed IO)
//   Hs: row-major [32][512] (reads are warp-broadcast; writes lane-consecutive)
//   Us: k-major [16][32]

#define NSTEPS   20
#define TM       32
#define LATENT   256
#define UDIM     16
#define HIDDEN   512
#define ZS_STRIDE 33
#define THREADS  256

__global__ __launch_bounds__(THREADS, 2)
void node_euler_kernel(const float* __restrict__ zt,
                       const float* __restrict__ dt,
                       const float* __restrict__ ut,
                       const float* __restrict__ W1,
                       const float* __restrict__ b1,
                       const float* __restrict__ W2,
                       const float* __restrict__ b2,
                       float* __restrict__ out)
{
    extern __shared__ float smem[];
    float* Zs    = smem;                               // [LATENT][ZS_STRIDE]
    float* Hs    = Zs + LATENT * ZS_STRIDE;            // [TM][HIDDEN]
    float* Us    = Hs + TM * HIDDEN;                   // [UDIM][TM]
    float* hstep = Us + UDIM * TM;                     // [TM]

    const int tid  = threadIdx.x;
    const int tx   = tid & 31;        // 0..31 (lane)
    const int ty   = tid >> 5;        // 0..7  (warp)
    const int row0 = blockIdx.x * TM;

    // ---- Load z tile (transposed into k-major Zs) ----
    for (int idx = tid; idx < TM * LATENT; idx += THREADS) {
        int r = idx >> 8;           // idx / 256
        int k = idx & 255;          // idx % 256
        Zs[k * ZS_STRIDE + r] = zt[(row0 + r) * LATENT + k];
    }
    // ---- Load u tile (k-major) ----
    for (int idx = tid; idx < TM * UDIM; idx += THREADS) {
        int r = idx >> 4;
        int k = idx & 15;
        Us[k * TM + r] = ut[(row0 + r) * UDIM + k];
    }
    // ---- Per-row step size h = dt/NSTEPS ----
    if (tid < TM) hstep[tid] = dt[row0 + tid] * (1.0f / NSTEPS);
    __syncthreads();

    const int rbase = ty * 4;   // this thread's 4 rows

    for (int s = 0; s < NSTEPS; s++) {
        // ================= GEMM1: H = tanh(X @ W1 + b1) =================
        // Thread tile: 4 rows x 16 cols (cols = tx + 32*j), 64 accumulators.
        float acc[16][4];
        #pragma unroll
        for (int j = 0; j < 16; j++) {
            float bv = b1[tx + 32 * j];
            #pragma unroll
            for (int r = 0; r < 4; r++) acc[j][r] = bv;
        }

        // K over latent part (z)
        #pragma unroll 2
        for (int k = 0; k < LATENT; k++) {
            float xr[4];
            #pragma unroll
            for (int r = 0; r < 4; r++)
                xr[r] = Zs[k * ZS_STRIDE + rbase + r];  // warp-broadcast
            const float* w = W1 + k * HIDDEN + tx;
            #pragma unroll
            for (int j = 0; j < 16; j++) {
                float wv = __ldg(w + 32 * j);            // 128B coalesced
                #pragma unroll
                for (int r = 0; r < 4; r++) acc[j][r] += wv * xr[r];
            }
        }
        // K over control part (u)
        #pragma unroll
        for (int k = 0; k < UDIM; k++) {
            float xr[4];
            #pragma unroll
            for (int r = 0; r < 4; r++)
                xr[r] = Us[k * TM + rbase + r];
            const float* w = W1 + (LATENT + k) * HIDDEN + tx;
            #pragma unroll
            for (int j = 0; j < 16; j++) {
                float wv = __ldg(w + 32 * j);
                #pragma unroll
                for (int r = 0; r < 4; r++) acc[j][r] += wv * xr[r];
            }
        }

        // tanh + store H (row-major; lanes write consecutive floats)
        #pragma unroll
        for (int j = 0; j < 16; j++) {
            #pragma unroll
            for (int r = 0; r < 4; r++) {
                Hs[(rbase + r) * HIDDEN + tx + 32 * j] = tanhf(acc[j][r]);
            }
        }
        __syncthreads();

        // ================= GEMM2: F = H @ W2 + b2;  z += h*F =================
        // Thread tile: 4 rows x 8 cols (cols = tx + 32*j), 32 accumulators.
        float acc2[8][4];
        #pragma unroll
        for (int j = 0; j < 8; j++) {
            float bv = b2[tx + 32 * j];
            #pragma unroll
            for (int r = 0; r < 4; r++) acc2[j][r] = bv;
        }

        #pragma unroll 2
        for (int k = 0; k < HIDDEN; k++) {
            float hr[4];
            #pragma unroll
            for (int r = 0; r < 4; r++)
                hr[r] = Hs[(rbase + r) * HIDDEN + k];    // warp-broadcast
            const float* w = W2 + k * LATENT + tx;
            #pragma unroll
            for (int j = 0; j < 8; j++) {
                float wv = __ldg(w + 32 * j);            // 128B coalesced
                #pragma unroll
                for (int r = 0; r < 4; r++) acc2[j][r] += wv * hr[r];
            }
        }

        // z update: Zs[col][row] += h[row] * F   (bank stride 33 -> conflict-free)
        #pragma unroll
        for (int j = 0; j < 8; j++) {
            int col = tx + 32 * j;
            #pragma unroll
            for (int r = 0; r < 4; r++) {
                int rr = rbase + r;
                Zs[col * ZS_STRIDE + rr] += hstep[rr] * acc2[j][r];
            }
        }
        __syncthreads();
    }

    // ---- Store z tile back (coalesced writes) ----
    for (int idx = tid; idx < TM * LATENT; idx += THREADS) {
        int r = idx >> 8;
        int k = idx & 255;
        out[(row0 + r) * LATENT + k] = Zs[k * ZS_STRIDE + r];
    }
}

extern "C" void kernel_launch(void* const* d_in, const int* in_sizes, int n_in,
                              void* d_out, int out_size)
{
    const float* zt = (const float*)d_in[0];
    const float* dt = (const float*)d_in[1];
    const float* ut = (const float*)d_in[2];
    const float* W1 = (const float*)d_in[3];
    const float* b1 = (const float*)d_in[4];
    const float* W2 = (const float*)d_in[5];
    const float* b2 = (const float*)d_in[6];
    float* out = (float*)d_out;

    const int B = 8192;
    const int grid = B / TM;   // 256 CTAs

    size_t smem_bytes = (size_t)(LATENT * ZS_STRIDE + TM * HIDDEN + UDIM * TM + TM) * sizeof(float);

    cudaFuncSetAttribute(node_euler_kernel,
                         cudaFuncAttributeMaxDynamicSharedMemorySize,
                         (int)smem_bytes);

    node_euler_kernel<<<grid, THREADS, smem_bytes>>>(zt, dt, ut, W1, b1, W2, b2, out);
}